// round 11
// baseline (speedup 1.0000x reference)
#include <cuda_runtime.h>
#include <cstdint>

#define N_    16
#define CIN_  512
#define COUT_ 512
#define STY_  512
#define H_    64
#define W_    64
#define HW_   (H_*W_)
#define QW_   66
#define QTOT_ (QW_*QW_)          /* 4356 padded pixels per image */

// ---------------- static device scratch (no allocation allowed) -------------
__device__ float g_s[N_*CIN_];                       // style modulation
__device__ float g_wsum2[CIN_*COUT_];                // [ci][co] sum_k w^2
__device__ float g_demod[N_*COUT_];                  // demod scale
__device__ float g_wk[9*COUT_*CIN_];                 // [k][co][ci] tf32 weights
__device__ float g_xt[(size_t)N_*QTOT_*CIN_];        // [n][q][ci] padded, premul, tf32

// ---------------- helpers ---------------------------------------------------
__device__ __forceinline__ uint32_t smem_u32(const void* p) {
    uint32_t a;
    asm("{ .reg .u64 t; cvta.to.shared.u64 t, %1; cvt.u32.u64 %0, t; }"
        : "=r"(a) : "l"(p));
    return a;
}
__device__ __forceinline__ float to_tf32(float v) {
    float r; asm("cvt.rna.tf32.f32 %0, %1;" : "=f"(r) : "f"(v)); return r;
}
__device__ __forceinline__ void cp16(uint32_t dst, const float* src) {
    asm volatile("cp.async.cg.shared.global [%0], [%1], 16;"
                 :: "r"(dst), "l"(src) : "memory");
}
#define CP_COMMIT() asm volatile("cp.async.commit_group;" ::: "memory")
#define CP_WAIT1()  asm volatile("cp.async.wait_group 1;" ::: "memory")

__device__ __forceinline__ void ldsm4(uint32_t* r, uint32_t addr) {
    asm volatile("ldmatrix.sync.aligned.m8n8.x4.shared.b16 {%0,%1,%2,%3}, [%4];"
        : "=r"(r[0]), "=r"(r[1]), "=r"(r[2]), "=r"(r[3]) : "r"(addr));
}
__device__ __forceinline__ void mma_tf32(float* d, const uint32_t* a, const uint32_t* b) {
    asm volatile("mma.sync.aligned.m16n8k8.row.col.f32.tf32.tf32.f32 "
        "{%0,%1,%2,%3}, {%4,%5,%6,%7}, {%8,%9}, {%0,%1,%2,%3};"
        : "+f"(d[0]), "+f"(d[1]), "+f"(d[2]), "+f"(d[3])
        : "r"(a[0]), "r"(a[1]), "r"(a[2]), "r"(a[3]), "r"(b[0]), "r"(b[1]));
}

// ---------------------------------------------------------------------------
// 1) s[n][ci] = style[n] . style_w[ci] + style_b[ci]
// ---------------------------------------------------------------------------
__global__ void style_kernel(const float* __restrict__ style,
                             const float* __restrict__ style_w,
                             const float* __restrict__ style_b) {
    __shared__ float ssty[STY_];
    int n = blockIdx.x;
    int ci = threadIdx.x;
    ssty[ci] = style[n*STY_ + ci];
    __syncthreads();
    const float* wr = style_w + ci*STY_;
    float acc = 0.f;
    #pragma unroll 8
    for (int k = 0; k < STY_; k++) acc += ssty[k] * wr[k];
    g_s[n*CIN_ + ci] = acc + style_b[ci];
}

// ---------------------------------------------------------------------------
// 2) wsum2[ci][co] = sum_k weight[co][ci][k]^2
// ---------------------------------------------------------------------------
__global__ void wsum2_kernel(const float* __restrict__ weight) {
    int idx = blockIdx.x*blockDim.x + threadIdx.x;
    if (idx >= COUT_*CIN_) return;
    int co = idx / CIN_, ci = idx % CIN_;
    const float* w = weight + (size_t)idx*9;
    float a = 0.f;
    #pragma unroll
    for (int k = 0; k < 9; k++) { float v = w[k]; a += v*v; }
    g_wsum2[ci*COUT_ + co] = a;
}

// ---------------------------------------------------------------------------
// 3) demod[n][co] = rsqrt( sum_ci s^2 * wsum2 + eps ) — split-K block reduce
// ---------------------------------------------------------------------------
__global__ void demod_kernel() {
    __shared__ float red[256];
    int n = blockIdx.x, cb = blockIdx.y;
    int co_l = threadIdx.x & 63, g = threadIdx.x >> 6;
    int co = cb*64 + co_l;
    const float* sp = g_s + n*CIN_;
    float acc = 0.f;
    #pragma unroll 16
    for (int ci = g*128; ci < g*128 + 128; ci++) {
        float s = sp[ci];
        acc += s*s*g_wsum2[ci*COUT_ + co];
    }
    red[threadIdx.x] = acc;
    __syncthreads();
    if (g == 0) {
        float t = red[co_l] + red[64+co_l] + red[128+co_l] + red[192+co_l] + 1e-8f;
        g_demod[n*COUT_ + co] = rsqrtf(t);
    }
}

// ---------------------------------------------------------------------------
// 4) weight repack: g_wk[k][co][ci] = tf32(weight[co][ci][k]) (ci contiguous)
//    smem transpose per co: coalesced read + coalesced write.
// ---------------------------------------------------------------------------
__global__ void pack_w_kernel(const float* __restrict__ w) {
    __shared__ float t[CIN_*9];
    int co = blockIdx.x;
    const float* src = w + (size_t)co*CIN_*9;
    for (int i = threadIdx.x; i < CIN_*9; i += 256)
        t[i] = to_tf32(src[i]);                  // t[ci*9+k]
    __syncthreads();
    for (int i = threadIdx.x; i < CIN_*9; i += 256) {
        int k = i >> 9, ci = i & (CIN_-1);
        g_wk[((size_t)k*COUT_ + co)*CIN_ + ci] = t[ci*9 + k];
    }
}

// ---------------------------------------------------------------------------
// 5) zero the padded border rows of g_xt (interior fully rewritten by pack_x)
// ---------------------------------------------------------------------------
__global__ void zero_border_kernel() {
    int b = blockIdx.x;
    int n = b / QTOT_, q = b % QTOT_;
    int y = q / QW_, xx = q % QW_;
    if (y != 0 && y != QW_-1 && xx != 0 && xx != QW_-1) return;
    float4 z = make_float4(0.f, 0.f, 0.f, 0.f);
    ((float4*)(g_xt + ((size_t)n*QTOT_ + q)*CIN_))[threadIdx.x] = z;
}

// ---------------------------------------------------------------------------
// 6) pack_x: transpose + premultiply + tf32-round into padded [n][q][ci]
// ---------------------------------------------------------------------------
__global__ void pack_x_kernel(const float* __restrict__ x) {
    __shared__ float t[32][65];
    int ci0 = blockIdx.x*32, y = blockIdx.y, n = blockIdx.z;
    int tid = threadIdx.x;
    for (int i = tid; i < 32*64; i += 256) {
        int cl = i >> 6, xx = i & 63;
        float v = x[(((size_t)n*CIN_ + ci0 + cl)*H_ + y)*W_ + xx]
                  * g_s[n*CIN_ + ci0 + cl];
        t[cl][xx] = to_tf32(v);
    }
    __syncthreads();
    int lane = tid & 31;
    for (int xx = tid >> 5; xx < 64; xx += 8) {
        int q = (y+1)*QW_ + xx + 1;
        g_xt[((size_t)n*QTOT_ + q)*CIN_ + ci0 + lane] = t[lane][xx];
    }
}

// ---------------------------------------------------------------------------
// 7) conv: ldmatrix + mma.sync tf32 shifted implicit GEMM
//    CTA 256co x 128px (2 rows), 8 warps (4m x 2n), warp tile 64x64.
//    SMEM rows = [row][32 ci] (128B), 16B-chunk XOR swizzle (c ^ row&7).
// ---------------------------------------------------------------------------
#define A_TILE_BYTES 32768                  /* 256 rows x 128B */
#define B_SLAB_BYTES (264*128)              /* 33792 */
#define OFF_B0 (2*A_TILE_BYTES)             /* 65536 */
#define SMEM_TOTAL (2*A_TILE_BYTES + 2*B_SLAB_BYTES)  /* 133120 */

__device__ __forceinline__ void load_A_tile(uint32_t dst, const float* gsrc, int tid) {
    // 256 co rows x 32 ci floats (128B/row, global row stride CIN_)
    #pragma unroll
    for (int i = 0; i < 8; i++) {
        int f = tid + i*256;                    // 0..2047
        int row = f >> 3, c = f & 7;
        cp16(dst + (uint32_t)(row*32 + ((c ^ (row & 7)) << 2))*4,
             gsrc + (size_t)row*CIN_ + c*4);
    }
}
__device__ __forceinline__ void load_B_slab(uint32_t dst, const float* gsrc, int tid) {
    // 264 q rows x 32 ci floats
    #pragma unroll
    for (int i = 0; i < 9; i++) {
        int f = tid + i*256;
        if (f < 2112) {
            int row = f >> 3, c = f & 7;
            cp16(dst + (uint32_t)(row*32 + ((c ^ (row & 7)) << 2))*4,
                 gsrc + (size_t)row*CIN_ + c*4);
        }
    }
}

__global__ __launch_bounds__(256, 1)
void conv_mma_kernel(const float* __restrict__ noise,
                     const float* __restrict__ noise_w,
                     float* __restrict__ out) {
    extern __shared__ char smem[];
    const uint32_t sb = smem_u32(smem);
    const int tid  = threadIdx.x;
    const int wid  = tid >> 5;
    const int lane = tid & 31;
    const int warp_m = wid & 3;            // 4 m-warps (co)
    const int warp_n = wid >> 2;           // 2 n-warps (px rows)
    const int co0 = blockIdx.x * 256;
    const int y0  = blockIdx.y * 2;        // 2 output rows per CTA
    const int n   = blockIdx.z;

    const float* wbase = g_wk + (size_t)co0*CIN_;   // + (k*COUT)*CIN + chunk*32
    const float* bbase = g_xt + ((size_t)n*QTOT_ + (size_t)y0*QW_)*CIN_;

    float acc[4][8][4];
    #pragma unroll
    for (int a = 0; a < 4; a++)
        #pragma unroll
        for (int b = 0; b < 8; b++)
            #pragma unroll
            for (int c = 0; c < 4; c++) acc[a][b][c] = 0.f;

    // ldmatrix lane geometry (PTX m8n8.x4: lane l -> matrix l>>3, row l&7)
    // A x4 per mt: m0=(rows g, chunk lo) m1=(g+8, lo) m2=(g, hi) m3=(g+8, hi)
    int a_row[4], a_rc[4];
    const int acb = lane >> 4;                       // chunk bit
    #pragma unroll
    for (int mt = 0; mt < 4; mt++) {
        a_row[mt] = warp_m*64 + mt*16 + ((lane>>3)&1)*8 + (lane&7);
        a_rc[mt]  = a_row[mt] & 7;
    }
    // B x4 per nt2: m0=(px grp0, lo) m1=(grp0, hi) m2=(grp1, lo) m3=(grp1, hi)
    const int b_sub = ((lane>>4)<<3) + (lane&7);     // px offset within 16
    const int bcb   = (lane>>3)&1;                   // chunk bit

    // prologue: prefetch B slab(chunk 0) + A tile(j=0)
    load_B_slab(sb + OFF_B0, bbase, tid);
    load_A_tile(sb, wbase, tid);
    CP_COMMIT();

    int chunk = 0, k9 = 0;
    for (int j = 0; j < 144; j++) {
        int nk9 = k9 + 1, nchunk = chunk;
        if (nk9 == 9) { nk9 = 0; nchunk++; }
        if (j < 143)
            load_A_tile(sb + ((j+1)&1)*A_TILE_BYTES,
                        wbase + (size_t)(nk9)*COUT_*CIN_ + (size_t)nchunk*32, tid);
        if (k9 == 0 && chunk + 1 < 16)
            load_B_slab(sb + OFF_B0 + ((chunk+1)&1)*B_SLAB_BYTES,
                        bbase + (size_t)(chunk+1)*32, tid);
        CP_COMMIT();
        CP_WAIT1();                        // data(j) resident
        __syncthreads();

        const uint32_t Abuf = sb + (j&1)*A_TILE_BYTES;
        const uint32_t Bbuf = sb + OFF_B0 + (chunk&1)*B_SLAB_BYTES;
        const int kh = k9 / 3, kw = k9 % 3;
        const int browc = (warp_n + kh)*QW_ + kw + b_sub;

        int b_row[4], b_rc[4];
        #pragma unroll
        for (int nt2 = 0; nt2 < 4; nt2++) {
            b_row[nt2] = browc + nt2*16;
            b_rc[nt2]  = b_row[nt2] & 7;
        }

        #pragma unroll
        for (int ks = 0; ks < 4; ks++) {
            const int ks2 = ks*2;
            uint32_t af[4][4], bf[4][4];
            #pragma unroll
            for (int mt = 0; mt < 4; mt++)
                ldsm4(af[mt], Abuf + (uint32_t)a_row[mt]*128
                                   + (uint32_t)(((ks2 + acb) ^ a_rc[mt]) << 4));
            #pragma unroll
            for (int nt2 = 0; nt2 < 4; nt2++)
                ldsm4(bf[nt2], Bbuf + (uint32_t)b_row[nt2]*128
                                    + (uint32_t)(((ks2 + bcb) ^ b_rc[nt2]) << 4));
            #pragma unroll
            for (int mt = 0; mt < 4; mt++)
                #pragma unroll
                for (int nt2 = 0; nt2 < 4; nt2++) {
                    mma_tf32(acc[mt][nt2*2],   af[mt], bf[nt2]);      // b0,b1
                    mma_tf32(acc[mt][nt2*2+1], af[mt], bf[nt2] + 2);  // b2,b3
                }
        }
        __syncthreads();                   // before next iter overwrites buffers

        k9 = nk9; chunk = nchunk;
    }

    // ---- epilogue: demod, noise, LeakyReLU(0.2) ----
    const int g = lane >> 2, t = lane & 3;
    const float nw = noise_w[0];
    const int orow = y0 + warp_n;
    const float* np_row = noise + ((size_t)n*H_ + orow)*W_;
    #pragma unroll
    for (int mt = 0; mt < 4; mt++) {
        int co_a = co0 + warp_m*64 + mt*16 + g;
        float dm0 = g_demod[n*COUT_ + co_a];
        float dm1 = g_demod[n*COUT_ + co_a + 8];
        float* o0 = out + (((size_t)n*COUT_ + co_a)*H_ + orow)*W_;
        float* o1 = o0 + (size_t)8*HW_;
        #pragma unroll
        for (int nt = 0; nt < 8; nt++) {
            int c = nt*8 + 2*t;
            float n0 = np_row[c], n1 = np_row[c+1];
            float v0 = acc[mt][nt][0]*dm0 + nw*n0; v0 = fmaxf(v0, 0.2f*v0);
            float v1 = acc[mt][nt][1]*dm0 + nw*n1; v1 = fmaxf(v1, 0.2f*v1);
            float v2 = acc[mt][nt][2]*dm1 + nw*n0; v2 = fmaxf(v2, 0.2f*v2);
            float v3 = acc[mt][nt][3]*dm1 + nw*n1; v3 = fmaxf(v3, 0.2f*v3);
            *(float2*)(o0 + c) = make_float2(v0, v1);
            *(float2*)(o1 + c) = make_float2(v2, v3);
        }
    }
}

// ---------------------------------------------------------------------------
// Inputs: x, style, noise, weight, style_w, style_b, noise_weight
// ---------------------------------------------------------------------------
extern "C" void kernel_launch(void* const* d_in, const int* in_sizes, int n_in,
                              void* d_out, int out_size) {
    const float* x        = (const float*)d_in[0];
    const float* style    = (const float*)d_in[1];
    const float* noise    = (const float*)d_in[2];
    const float* weight   = (const float*)d_in[3];
    const float* style_w  = (const float*)d_in[4];
    const float* style_b  = (const float*)d_in[5];
    const float* noise_w  = (const float*)d_in[6];
    float* out = (float*)d_out;

    style_kernel<<<N_, STY_>>>(style, style_w, style_b);
    wsum2_kernel<<<(COUT_*CIN_)/256, 256>>>(weight);
    demod_kernel<<<dim3(N_, COUT_/64), 256>>>();
    pack_w_kernel<<<COUT_, 256>>>(weight);
    zero_border_kernel<<<N_*QTOT_, 128>>>();
    pack_x_kernel<<<dim3(CIN_/32, H_, N_), 256>>>(x);

    cudaFuncSetAttribute(conv_mma_kernel,
                         cudaFuncAttributeMaxDynamicSharedMemorySize, SMEM_TOTAL);
    conv_mma_kernel<<<dim3(COUT_/256, H_/2, N_), 256, SMEM_TOTAL>>>(noise, noise_w, out);
}

// round 13
// speedup vs baseline: 1.6183x; 1.6183x over previous
#include <cuda_runtime.h>
#include <cstdint>

#define N_    16
#define CIN_  512
#define COUT_ 512
#define STY_  512
#define H_    64
#define W_    64
#define HW_   (H_*W_)
#define QW_   66
#define QTOT_ (QW_*QW_)          /* 4356 padded pixels per image */

// ---------------- static device scratch (no allocation allowed) -------------
__device__ float g_s[N_*CIN_];                       // style modulation
__device__ float g_wsum2[CIN_*COUT_];                // [ci][co] sum_k w^2
__device__ float g_demod[N_*COUT_];                  // demod scale
__device__ float g_wkf[9*CIN_*COUT_];                // fragment-ordered tf32 weights
__device__ float g_xt2[(size_t)N_*CIN_*QTOT_];       // [n][ci][q] padded, premul, tf32

// ---------------- helpers ---------------------------------------------------
__device__ __forceinline__ uint32_t smem_u32(const void* p) {
    uint32_t a;
    asm("{ .reg .u64 t; cvta.to.shared.u64 t, %1; cvt.u32.u64 %0, t; }"
        : "=r"(a) : "l"(p));
    return a;
}
__device__ __forceinline__ float to_tf32(float v) {
    float r; asm("cvt.rna.tf32.f32 %0, %1;" : "=f"(r) : "f"(v)); return r;
}
__device__ __forceinline__ void cp16(uint32_t dst, const float* src) {
    asm volatile("cp.async.cg.shared.global [%0], [%1], 16;"
                 :: "r"(dst), "l"(src) : "memory");
}
#define CP_COMMIT() asm volatile("cp.async.commit_group;" ::: "memory")
#define CP_WAIT1()  asm volatile("cp.async.wait_group 1;" ::: "memory")

__device__ __forceinline__ void mma_tf32(float* d, const uint32_t* a, const uint32_t* b) {
    asm volatile("mma.sync.aligned.m16n8k8.row.col.f32.tf32.tf32.f32 "
        "{%0,%1,%2,%3}, {%4,%5,%6,%7}, {%8,%9}, {%0,%1,%2,%3};"
        : "+f"(d[0]), "+f"(d[1]), "+f"(d[2]), "+f"(d[3])
        : "r"(a[0]), "r"(a[1]), "r"(a[2]), "r"(a[3]), "r"(b[0]), "r"(b[1]));
}

// ---------------------------------------------------------------------------
// 1) s[n][ci] = style[n] . style_w[ci] + style_b[ci]
// ---------------------------------------------------------------------------
__global__ void style_kernel(const float* __restrict__ style,
                             const float* __restrict__ style_w,
                             const float* __restrict__ style_b) {
    __shared__ float ssty[STY_];
    int n = blockIdx.x;
    int ci = threadIdx.x;
    ssty[ci] = style[n*STY_ + ci];
    __syncthreads();
    const float* wr = style_w + ci*STY_;
    float acc = 0.f;
    #pragma unroll 8
    for (int k = 0; k < STY_; k++) acc += ssty[k] * wr[k];
    g_s[n*CIN_ + ci] = acc + style_b[ci];
}

// ---------------------------------------------------------------------------
// 2) wsum2[ci][co] = sum_k weight[co][ci][k]^2
// ---------------------------------------------------------------------------
__global__ void wsum2_kernel(const float* __restrict__ weight) {
    int idx = blockIdx.x*blockDim.x + threadIdx.x;
    if (idx >= COUT_*CIN_) return;
    int co = idx / CIN_, ci = idx % CIN_;
    const float* w = weight + (size_t)idx*9;
    float a = 0.f;
    #pragma unroll
    for (int k = 0; k < 9; k++) { float v = w[k]; a += v*v; }
    g_wsum2[ci*COUT_ + co] = a;
}

// ---------------------------------------------------------------------------
// 3) demod[n][co] = rsqrt( sum_ci s^2 * wsum2 + eps ) — split-K block reduce
// ---------------------------------------------------------------------------
__global__ void demod_kernel() {
    __shared__ float red[256];
    int n = blockIdx.x, cb = blockIdx.y;
    int co_l = threadIdx.x & 63, g = threadIdx.x >> 6;
    int co = cb*64 + co_l;
    const float* sp = g_s + n*CIN_;
    float acc = 0.f;
    #pragma unroll 16
    for (int ci = g*128; ci < g*128 + 128; ci++) {
        float s = sp[ci];
        acc += s*s*g_wsum2[ci*COUT_ + co];
    }
    red[threadIdx.x] = acc;
    __syncthreads();
    if (g == 0) {
        float t = red[co_l] + red[64+co_l] + red[128+co_l] + red[192+co_l] + 1e-8f;
        g_demod[n*COUT_ + co] = rsqrtf(t);
    }
}

// ---------------------------------------------------------------------------
// 4) weight repack into exact mma A-fragment order:
//    g_wkf[k][cs][chunk][ks][mtile][lane][e], e: (g,t)(g+8,t)(g,t+4)(g+8,t+4)
// ---------------------------------------------------------------------------
__global__ void pack_w_kernel(const float* __restrict__ w) {
    int f = blockIdx.x*256 + threadIdx.x;
    if (f >= 9*COUT_*CIN_) return;
    int e     = f & 3;
    int lane  = (f >> 2) & 31;
    int mtile = (f >> 7) & 7;
    int ks    = (f >> 10) & 3;
    int chunk = (f >> 12) & 15;
    int cs    = (f >> 16) & 3;
    int k     = f >> 18;
    int g = lane >> 2, t = lane & 3;
    int ci = chunk*32 + ks*8 + t + ((e >> 1) << 2);
    int co = cs*128 + mtile*16 + g + ((e & 1) << 3);
    g_wkf[f] = to_tf32(w[((size_t)co*CIN_ + ci)*9 + k]);
}

// ---------------------------------------------------------------------------
// 5) pack_x: premultiply + tf32 + zero-pad into [n][ci][qy*66+qx]
// ---------------------------------------------------------------------------
__global__ void pack_x_kernel(const float* __restrict__ x) {
    int plane = blockIdx.x;                 // n*CIN + ci
    int q = blockIdx.y*256 + threadIdx.x;
    if (q >= QTOT_) return;
    int qy = q / QW_, qx = q % QW_;
    float v = 0.f;
    if (qy >= 1 && qy <= H_ && qx >= 1 && qx <= W_) {
        float s = g_s[plane];               // plane IS n*512+ci
        v = to_tf32(x[(size_t)plane*HW_ + (qy-1)*W_ + (qx-1)] * s);
    }
    g_xt2[(size_t)plane*QTOT_ + q] = v;
}

// ---------------------------------------------------------------------------
// 6) conv: mma.sync tf32 shifted implicit GEMM + demod + noise + LeakyReLU
//    CTA 128co x 128px (2 rows), 8 warps (2m x 4n), warp tile 64x32.
//    A fragments pre-packed -> one LDS.128 per fragment.
// ---------------------------------------------------------------------------
#define B_STRIDE 264                       /* floats; 264%32==8 -> bank-safe */
#define A_BYTES  16384                     /* 4 ks x 8 mtile x 32 lane x 16B */
#define B_BYTES  (32*B_STRIDE*4)           /* 33792 */
#define B_OFF    (2*A_BYTES)               /* 32768 */
#define SMEM_TOTAL (2*A_BYTES + 2*B_BYTES) /* 100352 */

__device__ __forceinline__ void load_A_tile(uint32_t dst, const float* gsrc, int tid) {
    // 16 KB linear copy (fragment order already in GMEM)
    #pragma unroll
    for (int i = 0; i < 4; i++) {
        int f = tid + i*256;                    // 0..1023 16B chunks
        cp16(dst + (uint32_t)f*16, gsrc + (size_t)f*4);
    }
}
__device__ __forceinline__ void load_B_slab(uint32_t dst, const float* gsrc, int tid) {
    // 32 ci rows x 264 floats (contiguous per ci, global stride QTOT_)
    #pragma unroll
    for (int i = 0; i < 9; i++) {
        int f = tid + i*256;
        if (f < 2112) {
            int ci = f / 66, c4 = (f % 66) << 2;
            cp16(dst + (uint32_t)(ci*B_STRIDE + c4)*4, gsrc + (size_t)ci*QTOT_ + c4);
        }
    }
}

__global__ __launch_bounds__(256, 2)
void conv_mma_kernel(const float* __restrict__ noise,
                     const float* __restrict__ noise_w,
                     float* __restrict__ out) {
    extern __shared__ char smem[];
    const uint32_t sb = smem_u32(smem);
    const int tid  = threadIdx.x;
    const int wid  = tid >> 5;
    const int lane = tid & 31;
    const int g    = lane >> 2;            // groupID
    const int t    = lane & 3;             // threadID_in_group
    const int warp_m = wid & 1;            // 2 m-warps
    const int warp_n = wid >> 1;           // 4 n-warps
    const int co0 = blockIdx.x * 128;
    const int y0  = blockIdx.y * 2;        // 2 output rows per CTA
    const int n   = blockIdx.z;

    // A source: g_wkf[k][cs=blockIdx.x][chunk] blocks of 4096 floats
    const float* wbase = g_wkf + (size_t)blockIdx.x*(16*4096);
    const float* bbase = g_xt2 + (size_t)n*CIN_*QTOT_ + (size_t)y0*QW_; // +ci*QTOT_

    float acc[4][4][4];
    #pragma unroll
    for (int a = 0; a < 4; a++)
        #pragma unroll
        for (int b = 0; b < 4; b++)
            #pragma unroll
            for (int c = 0; c < 4; c++) acc[a][b][c] = 0.f;

    // prologue: prefetch B slab(chunk 0) + A tile(j=0)
    load_B_slab(sb + B_OFF, bbase, tid);
    load_A_tile(sb, wbase, tid);
    CP_COMMIT();

    int chunk = 0, k9 = 0;
    for (int j = 0; j < 144; j++) {
        // ---- prefetch data for j+1 into alternate buffers ----
        int nk9 = k9 + 1, nchunk = chunk;
        if (nk9 == 9) { nk9 = 0; nchunk++; }
        if (j < 143)
            load_A_tile(sb + ((j+1)&1)*A_BYTES,
                        wbase + (size_t)nk9*(4*16*4096) + (size_t)nchunk*4096, tid);
        if (k9 == 0 && chunk + 1 < 16)
            load_B_slab(sb + B_OFF + ((chunk+1)&1)*B_BYTES,
                        bbase + (size_t)(chunk+1)*32*QTOT_, tid);
        CP_COMMIT();
        CP_WAIT1();                        // group for data(j) complete
        __syncthreads();

        const uint4* As = (const uint4*)(smem + (j&1)*A_BYTES);
        const float* Bs = (const float*)(smem + B_OFF + (chunk&1)*B_BYTES);
        const int kh = k9 / 3, kw = k9 % 3;
        const float* Bsh = Bs + kh*QW_ + kw;

        #pragma unroll
        for (int ks = 0; ks < 4; ks++) {
            uint4 af[4]; uint32_t bf[4][2];
            #pragma unroll
            for (int mt = 0; mt < 4; mt++)
                af[mt] = As[(ks*8 + warp_m*4 + mt)*32 + lane];
            const float* bk = Bsh + (ks*8 + t)*B_STRIDE;
            #pragma unroll
            for (int nt = 0; nt < 4; nt++) {
                int px0 = warp_n*32 + nt*8;
                int off = (px0 >> 6)*QW_ + (px0 & 63) + g;
                bf[nt][0] = __float_as_uint(bk[off]);               // (t,   g)
                bf[nt][1] = __float_as_uint(bk[off + 4*B_STRIDE]);  // (t+4, g)
            }
            #pragma unroll
            for (int mt = 0; mt < 4; mt++)
                #pragma unroll
                for (int nt = 0; nt < 4; nt++)
                    mma_tf32(acc[mt][nt], (const uint32_t*)&af[mt], bf[nt]);
        }
        __syncthreads();                   // before next iter overwrites buffers

        k9 = nk9; chunk = nchunk;
    }

    // ---- epilogue: demod, noise, LeakyReLU(0.2) ----
    const float nw = noise_w[0];
    #pragma unroll
    for (int mt = 0; mt < 4; mt++) {
        int co_a = co0 + warp_m*64 + mt*16 + g;
        float dm0 = g_demod[n*COUT_ + co_a];
        float dm1 = g_demod[n*COUT_ + co_a + 8];
        float* o0 = out + ((size_t)n*COUT_ + co_a)*HW_ + (size_t)y0*W_;
        float* o1 = o0 + (size_t)8*HW_;
        #pragma unroll
        for (int nt = 0; nt < 4; nt++) {
            int px0 = warp_n*32 + nt*8;
            int r = px0 >> 6;
            int c = (px0 & 63) + 2*t;
            const float* np = noise + ((size_t)n*H_ + y0 + r)*W_ + c;
            float n0 = np[0], n1 = np[1];
            float v0 = acc[mt][nt][0]*dm0 + nw*n0; v0 = fmaxf(v0, 0.2f*v0);
            float v1 = acc[mt][nt][1]*dm0 + nw*n1; v1 = fmaxf(v1, 0.2f*v1);
            float v2 = acc[mt][nt][2]*dm1 + nw*n0; v2 = fmaxf(v2, 0.2f*v2);
            float v3 = acc[mt][nt][3]*dm1 + nw*n1; v3 = fmaxf(v3, 0.2f*v3);
            *(float2*)(o0 + (size_t)r*W_ + c) = make_float2(v0, v1);
            *(float2*)(o1 + (size_t)r*W_ + c) = make_float2(v2, v3);
        }
    }
}

// ---------------------------------------------------------------------------
// Inputs: x, style, noise, weight, style_w, style_b, noise_weight
// ---------------------------------------------------------------------------
extern "C" void kernel_launch(void* const* d_in, const int* in_sizes, int n_in,
                              void* d_out, int out_size) {
    const float* x        = (const float*)d_in[0];
    const float* style    = (const float*)d_in[1];
    const float* noise    = (const float*)d_in[2];
    const float* weight   = (const float*)d_in[3];
    const float* style_w  = (const float*)d_in[4];
    const float* style_b  = (const float*)d_in[5];
    const float* noise_w  = (const float*)d_in[6];
    float* out = (float*)d_out;

    style_kernel<<<N_, STY_>>>(style, style_w, style_b);
    wsum2_kernel<<<(COUT_*CIN_)/256, 256>>>(weight);
    demod_kernel<<<dim3(N_, COUT_/64), 256>>>();
    pack_w_kernel<<<(9*COUT_*CIN_ + 255)/256, 256>>>(weight);
    pack_x_kernel<<<dim3(N_*CIN_, (QTOT_+255)/256), 256>>>(x);

    cudaFuncSetAttribute(conv_mma_kernel,
                         cudaFuncAttributeMaxDynamicSharedMemorySize, SMEM_TOTAL);
    conv_mma_kernel<<<dim3(COUT_/128, H_/2, N_), 256, SMEM_TOTAL>>>(noise, noise_w, out);
}

// round 14
// speedup vs baseline: 2.7740x; 1.7142x over previous
#include <cuda_runtime.h>
#include <cuda_fp16.h>
#include <cstdint>

#define N_    16
#define CIN_  512
#define COUT_ 512
#define STY_  512
#define H_    64
#define W_    64
#define HW_   (H_*W_)
#define QW_   66
#define QTOT_ (QW_*QW_)          /* 4356 padded pixels per image */
#define CP2_  (CIN_/2)           /* 256 ci pairs */

// ---------------- static device scratch (no allocation allowed) -------------
__device__ float    g_s[N_*CIN_];                    // style modulation
__device__ float    g_wsum2[CIN_*COUT_];             // [ci][co] sum_k w^2
__device__ float    g_demod[N_*COUT_];               // demod scale
__device__ uint32_t g_whf[9*COUT_*CIN_/2];           // fragment-ordered fp16x2 weights
__device__ uint32_t g_xh[(size_t)N_*CP2_*QTOT_];     // [n][cipair][q] fp16x2, premul

// ---------------- helpers ---------------------------------------------------
__device__ __forceinline__ uint32_t smem_u32(const void* p) {
    uint32_t a;
    asm("{ .reg .u64 t; cvta.to.shared.u64 t, %1; cvt.u32.u64 %0, t; }"
        : "=r"(a) : "l"(p));
    return a;
}
__device__ __forceinline__ void cp16(uint32_t dst, const void* src) {
    asm volatile("cp.async.cg.shared.global [%0], [%1], 16;"
                 :: "r"(dst), "l"(src) : "memory");
}
#define CP_COMMIT() asm volatile("cp.async.commit_group;" ::: "memory")
#define CP_WAIT1()  asm volatile("cp.async.wait_group 1;" ::: "memory")

__device__ __forceinline__ void mma_f16(float* d, const uint32_t* a, const uint32_t* b) {
    asm volatile("mma.sync.aligned.m16n8k16.row.col.f32.f16.f16.f32 "
        "{%0,%1,%2,%3}, {%4,%5,%6,%7}, {%8,%9}, {%0,%1,%2,%3};"
        : "+f"(d[0]), "+f"(d[1]), "+f"(d[2]), "+f"(d[3])
        : "r"(a[0]), "r"(a[1]), "r"(a[2]), "r"(a[3]), "r"(b[0]), "r"(b[1]));
}

// ---------------------------------------------------------------------------
// 1) s[n][ci] = style[n] . style_w[ci] + style_b[ci]
// ---------------------------------------------------------------------------
__global__ void style_kernel(const float* __restrict__ style,
                             const float* __restrict__ style_w,
                             const float* __restrict__ style_b) {
    __shared__ float ssty[STY_];
    int n = blockIdx.x;
    int ci = threadIdx.x;
    ssty[ci] = style[n*STY_ + ci];
    __syncthreads();
    const float* wr = style_w + ci*STY_;
    float acc = 0.f;
    #pragma unroll 8
    for (int k = 0; k < STY_; k++) acc += ssty[k] * wr[k];
    g_s[n*CIN_ + ci] = acc + style_b[ci];
}

// ---------------------------------------------------------------------------
// 2) wsum2[ci][co] = sum_k weight[co][ci][k]^2
// ---------------------------------------------------------------------------
__global__ void wsum2_kernel(const float* __restrict__ weight) {
    int idx = blockIdx.x*blockDim.x + threadIdx.x;
    if (idx >= COUT_*CIN_) return;
    int co = idx / CIN_, ci = idx % CIN_;
    const float* w = weight + (size_t)idx*9;
    float a = 0.f;
    #pragma unroll
    for (int k = 0; k < 9; k++) { float v = w[k]; a += v*v; }
    g_wsum2[ci*COUT_ + co] = a;
}

// ---------------------------------------------------------------------------
// 3) demod[n][co] = rsqrt( sum_ci s^2 * wsum2 + eps ) — split-K block reduce
// ---------------------------------------------------------------------------
__global__ void demod_kernel() {
    __shared__ float red[256];
    int n = blockIdx.x, cb = blockIdx.y;
    int co_l = threadIdx.x & 63, g = threadIdx.x >> 6;
    int co = cb*64 + co_l;
    const float* sp = g_s + n*CIN_;
    float acc = 0.f;
    #pragma unroll 16
    for (int ci = g*128; ci < g*128 + 128; ci++) {
        float s = sp[ci];
        acc += s*s*g_wsum2[ci*COUT_ + co];
    }
    red[threadIdx.x] = acc;
    __syncthreads();
    if (g == 0) {
        float t = red[co_l] + red[64+co_l] + red[128+co_l] + red[192+co_l] + 1e-8f;
        g_demod[n*COUT_ + co] = rsqrtf(t);
    }
}

// ---------------------------------------------------------------------------
// 4) weight repack -> fp16x2 in exact m16n8k16 A-fragment order:
//    u = [k][cs][chunk][ks(2)][mtile(8)][lane(32)][e(4)]
//    e: a0=(g, 2t..2t+1) a1=(g+8, ..) a2=(g, 2t+8..) a3=(g+8, 2t+8..)
// ---------------------------------------------------------------------------
__global__ void pack_w_kernel(const float* __restrict__ w) {
    int u = blockIdx.x*256 + threadIdx.x;
    if (u >= 9*COUT_*CIN_/2) return;
    int e     = u & 3;
    int lane  = (u >> 2) & 31;
    int mtile = (u >> 7) & 7;
    int ks    = (u >> 10) & 1;
    int chunk = (u >> 11) & 15;
    int cs    = (u >> 15) & 3;
    int k     = u >> 17;
    int g = lane >> 2, t = lane & 3;
    int ci = chunk*32 + ks*16 + 2*t + ((e >> 1) << 3);
    int co = cs*128 + mtile*16 + g + ((e & 1) << 3);
    float v0 = w[((size_t)co*CIN_ + ci)*9 + k];
    float v1 = w[((size_t)co*CIN_ + ci + 1)*9 + k];
    half2 h = __floats2half2_rn(v0, v1);
    g_whf[u] = *(uint32_t*)&h;
}

// ---------------------------------------------------------------------------
// 5) pack_x: premultiply + fp16x2 ci-pairing + zero-pad into [n][cp][q]
// ---------------------------------------------------------------------------
__global__ void pack_x_kernel(const float* __restrict__ x) {
    int pp = blockIdx.x;                    // n*CP2 + cp
    int q = blockIdx.y*256 + threadIdx.x;
    if (q >= QTOT_) return;
    int n = pp >> 8, cp = pp & (CP2_-1);
    int qy = q / QW_, qx = q % QW_;
    uint32_t out = 0;
    if (qy >= 1 && qy <= H_ && qx >= 1 && qx <= W_) {
        size_t base = ((size_t)n*CIN_ + 2*cp)*HW_ + (qy-1)*W_ + (qx-1);
        float s0 = g_s[n*CIN_ + 2*cp], s1 = g_s[n*CIN_ + 2*cp + 1];
        half2 h = __floats2half2_rn(x[base]*s0, x[base + HW_]*s1);
        out = *(uint32_t*)&h;
    }
    g_xh[(size_t)pp*QTOT_ + q] = out;
}

// ---------------------------------------------------------------------------
// 6) conv: mma.sync fp16 m16n8k16 shifted implicit GEMM
//    CTA 128co x 128px (2 rows), 8 warps (2m x 4n), warp tile 64x32.
//    144 iters = 16 ci-chunks x 9 shifts, cp.async double-buffered.
// ---------------------------------------------------------------------------
#define B_STRIDE 264                       /* uint32; 264%32==8 -> bank-safe */
#define A_BYTES  8192                      /* 2 ks x 8 mt x 32 lane x 16B */
#define B_BYTES  (16*B_STRIDE*4)           /* 16896 */
#define B_OFF    (2*A_BYTES)               /* 16384 */
#define SMEM_TOTAL (2*A_BYTES + 2*B_BYTES) /* 50176 */

__device__ __forceinline__ void load_A_tile(uint32_t dst, const uint32_t* gsrc, int tid) {
    // 8 KB linear copy (fragment order already in GMEM)
    #pragma unroll
    for (int i = 0; i < 2; i++) {
        int f = tid + i*256;                    // 0..511 16B chunks
        cp16(dst + (uint32_t)f*16, gsrc + (size_t)f*4);
    }
}
__device__ __forceinline__ void load_B_slab(uint32_t dst, const uint32_t* gsrc, int tid) {
    // 16 pair-rows x 264 uint32 (contiguous per row, global stride QTOT_)
    #pragma unroll
    for (int i = 0; i < 5; i++) {
        int f = tid + i*256;
        if (f < 1056) {
            int row = f / 66, c4 = (f % 66) << 2;
            cp16(dst + (uint32_t)(row*B_STRIDE + c4)*4, gsrc + (size_t)row*QTOT_ + c4);
        }
    }
}

__global__ __launch_bounds__(256, 2)
void conv_mma_kernel(const float* __restrict__ noise,
                     const float* __restrict__ noise_w,
                     float* __restrict__ out) {
    extern __shared__ char smem[];
    const uint32_t sb = smem_u32(smem);
    const int tid  = threadIdx.x;
    const int wid  = tid >> 5;
    const int lane = tid & 31;
    const int g    = lane >> 2;            // groupID
    const int t    = lane & 3;             // threadID_in_group
    const int warp_m = wid & 1;            // 2 m-warps
    const int warp_n = wid >> 1;           // 4 n-warps
    const int co0 = blockIdx.x * 128;
    const int y0  = blockIdx.y * 2;        // 2 output rows per CTA
    const int n   = blockIdx.z;

    // A: g_whf[k][cs=blockIdx.x][chunk] blocks of 2048 uint32 (8 KB)
    const uint32_t* wbase = g_whf + (size_t)blockIdx.x*(16*2048);
    const uint32_t* bbase = g_xh + (size_t)n*CP2_*QTOT_ + (size_t)y0*QW_; // +cp*QTOT_

    float acc[4][4][4];
    #pragma unroll
    for (int a = 0; a < 4; a++)
        #pragma unroll
        for (int b = 0; b < 4; b++)
            #pragma unroll
            for (int c = 0; c < 4; c++) acc[a][b][c] = 0.f;

    // prologue: prefetch B slab(chunk 0) + A tile(j=0)
    load_B_slab(sb + B_OFF, bbase, tid);
    load_A_tile(sb, wbase, tid);
    CP_COMMIT();

    int chunk = 0, k9 = 0;
    for (int j = 0; j < 144; j++) {
        // ---- prefetch data for j+1 into alternate buffers ----
        int nk9 = k9 + 1, nchunk = chunk;
        if (nk9 == 9) { nk9 = 0; nchunk++; }
        if (j < 143)
            load_A_tile(sb + ((j+1)&1)*A_BYTES,
                        wbase + (size_t)nk9*(4*16*2048) + (size_t)nchunk*2048, tid);
        if (k9 == 0 && chunk + 1 < 16)
            load_B_slab(sb + B_OFF + ((chunk+1)&1)*B_BYTES,
                        bbase + (size_t)(chunk+1)*16*QTOT_, tid);
        CP_COMMIT();
        CP_WAIT1();                        // group for data(j) complete
        __syncthreads();

        const uint4* As = (const uint4*)(smem + (j&1)*A_BYTES);
        const uint32_t* Bs = (const uint32_t*)(smem + B_OFF + (chunk&1)*B_BYTES);
        const int kh = k9 / 3, kw = k9 % 3;
        const int shoff = kh*QW_ + kw + g;

        #pragma unroll
        for (int ks = 0; ks < 2; ks++) {
            uint4 af[4]; uint32_t bf[4][2];
            #pragma unroll
            for (int mt = 0; mt < 4; mt++)
                af[mt] = As[(ks*8 + warp_m*4 + mt)*32 + lane];
            const uint32_t* bk = Bs + (ks*8 + t)*B_STRIDE + shoff;
            #pragma unroll
            for (int nt = 0; nt < 4; nt++) {
                int px0 = warp_n*32 + nt*8;
                int off = (px0 >> 6)*QW_ + (px0 & 63);
                bf[nt][0] = bk[off];                   // pairs (k=2t,2t+1)   @ px g
                bf[nt][1] = bk[off + 4*B_STRIDE];      // pairs (k=2t+8,2t+9) @ px g
            }
            #pragma unroll
            for (int mt = 0; mt < 4; mt++)
                #pragma unroll
                for (int nt = 0; nt < 4; nt++)
                    mma_f16(acc[mt][nt], (const uint32_t*)&af[mt], bf[nt]);
        }
        __syncthreads();                   // before next iter overwrites buffers

        k9 = nk9; chunk = nchunk;
    }

    // ---- epilogue: demod, noise, LeakyReLU(0.2) ----
    const float nw = noise_w[0];
    #pragma unroll
    for (int mt = 0; mt < 4; mt++) {
        int co_a = co0 + warp_m*64 + mt*16 + g;
        float dm0 = g_demod[n*COUT_ + co_a];
        float dm1 = g_demod[n*COUT_ + co_a + 8];
        float* o0 = out + ((size_t)n*COUT_ + co_a)*HW_ + (size_t)y0*W_;
        float* o1 = o0 + (size_t)8*HW_;
        #pragma unroll
        for (int nt = 0; nt < 4; nt++) {
            int px0 = warp_n*32 + nt*8;
            int r = px0 >> 6;
            int c = (px0 & 63) + 2*t;
            const float* np = noise + ((size_t)n*H_ + y0 + r)*W_ + c;
            float n0 = np[0], n1 = np[1];
            float v0 = acc[mt][nt][0]*dm0 + nw*n0; v0 = fmaxf(v0, 0.2f*v0);
            float v1 = acc[mt][nt][1]*dm0 + nw*n1; v1 = fmaxf(v1, 0.2f*v1);
            float v2 = acc[mt][nt][2]*dm1 + nw*n0; v2 = fmaxf(v2, 0.2f*v2);
            float v3 = acc[mt][nt][3]*dm1 + nw*n1; v3 = fmaxf(v3, 0.2f*v3);
            *(float2*)(o0 + (size_t)r*W_ + c) = make_float2(v0, v1);
            *(float2*)(o1 + (size_t)r*W_ + c) = make_float2(v2, v3);
        }
    }
}

// ---------------------------------------------------------------------------
// Inputs: x, style, noise, weight, style_w, style_b, noise_weight
// ---------------------------------------------------------------------------
extern "C" void kernel_launch(void* const* d_in, const int* in_sizes, int n_in,
                              void* d_out, int out_size) {
    const float* x        = (const float*)d_in[0];
    const float* style    = (const float*)d_in[1];
    const float* noise    = (const float*)d_in[2];
    const float* weight   = (const float*)d_in[3];
    const float* style_w  = (const float*)d_in[4];
    const float* style_b  = (const float*)d_in[5];
    const float* noise_w  = (const float*)d_in[6];
    float* out = (float*)d_out;

    style_kernel<<<N_, STY_>>>(style, style_w, style_b);
    wsum2_kernel<<<(COUT_*CIN_)/256, 256>>>(weight);
    demod_kernel<<<dim3(N_, COUT_/64), 256>>>();
    pack_w_kernel<<<(9*COUT_*CIN_/2 + 255)/256, 256>>>(weight);
    pack_x_kernel<<<dim3(N_*CP2_, (QTOT_+255)/256), 256>>>(x);

    cudaFuncSetAttribute(conv_mma_kernel,
                         cudaFuncAttributeMaxDynamicSharedMemorySize, SMEM_TOTAL);
    conv_mma_kernel<<<dim3(COUT_/128, H_/2, N_), 256, SMEM_TOTAL>>>(noise, noise_w, out);
}